// round 9
// baseline (speedup 1.0000x reference)
#include <cuda_runtime.h>
#include <cuda_bf16.h>
#include <mma.h>
#include <math.h>

using namespace nvcuda;

#define NMAX 100000
#define EMAX 1600000
#define DF   128
#define SCAN_B 1024

// Scratch (__device__ globals; allocation is forbidden).
__device__ float g_agg1[(size_t)NMAX * DF];
__device__ float g_agg2[(size_t)NMAX * DF];
__device__ __align__(16) __nv_bfloat16 g_Wh[3 * 16384];  // row-major [ch][j][k] hi
__device__ __align__(16) __nv_bfloat16 g_Wl[3 * 16384];  // row-major [ch][j][k] lo
__device__ int   g_idx64;
__device__ int   g_cnt[NMAX];
__device__ int   g_scan[NMAX];
__device__ int   g_bsum[1024];
__device__ int   g_rowptr[NMAX + 1];
__device__ int   g_esrc[EMAX];

// ---------------------------------------------------------------------------
// Edge-index dtype detection
// ---------------------------------------------------------------------------
__global__ void detect_idx_kernel(const unsigned* __restrict__ ei_raw) {
    if (threadIdx.x == 0 && blockIdx.x == 0) {
        unsigned acc = 0;
        for (int i = 0; i < 64; i++) acc |= ei_raw[2 * i + 1];
        g_idx64 = (acc == 0u) ? 1 : 0;
    }
}

__device__ __forceinline__ int load_idx(const int* __restrict__ ei32,
                                        long long pos, int idx64) {
    return idx64 ? ei32[2 * pos] : ei32[pos];
}

// ---------------------------------------------------------------------------
// CSR build
// ---------------------------------------------------------------------------
__global__ void cnt_zero_kernel(int* __restrict__ cnt, int n) {
    int i = blockIdx.x * blockDim.x + threadIdx.x;
    if (i < n) cnt[i] = 0;
}

__global__ void hist_kernel(const int* __restrict__ ei32, int* __restrict__ cnt,
                            long long E) {
    long long e = (long long)blockIdx.x * blockDim.x + threadIdx.x;
    if (e >= E) return;
    int dst = load_idx(ei32, e + E, g_idx64);
    atomicAdd(&cnt[dst], 1);
}

__global__ void scan_a_kernel(const int* __restrict__ cnt, int* __restrict__ scan,
                              int* __restrict__ bsum, int n) {
    __shared__ int sh[SCAN_B];
    int tid = threadIdx.x;
    int i = blockIdx.x * SCAN_B + tid;
    sh[tid] = (i < n) ? cnt[i] : 0;
    __syncthreads();
    for (int o = 1; o < SCAN_B; o <<= 1) {
        int t = (tid >= o) ? sh[tid - o] : 0;
        __syncthreads();
        if (tid >= o) sh[tid] += t;
        __syncthreads();
    }
    if (i < n) scan[i] = sh[tid];
    if (tid == SCAN_B - 1) bsum[blockIdx.x] = sh[tid];
}

__global__ void scan_b_kernel(int* __restrict__ bsum, int nb) {
    __shared__ int sh[1024];
    int tid = threadIdx.x;
    int v = (tid < nb) ? bsum[tid] : 0;
    sh[tid] = v;
    __syncthreads();
    for (int o = 1; o < 1024; o <<= 1) {
        int t = (tid >= o) ? sh[tid - o] : 0;
        __syncthreads();
        if (tid >= o) sh[tid] += t;
        __syncthreads();
    }
    if (tid < nb) bsum[tid] = sh[tid] - v;
}

__global__ void scan_c_kernel(const int* __restrict__ scan,
                              const int* __restrict__ bsum,
                              int* __restrict__ rowptr, int* __restrict__ cnt, int n) {
    int i = blockIdx.x * blockDim.x + threadIdx.x;
    if (i < n) {
        rowptr[i + 1] = scan[i] + bsum[i / SCAN_B];
        cnt[i] = 0;
    }
    if (i == 0) rowptr[0] = 0;
}

__global__ void fill_kernel(const int* __restrict__ ei32,
                            const int* __restrict__ rowptr,
                            int* __restrict__ cur, int* __restrict__ esrc,
                            long long E) {
    long long e = (long long)blockIdx.x * blockDim.x + threadIdx.x;
    if (e >= E) return;
    int idx64 = g_idx64;
    int src = load_idx(ei32, e, idx64);
    int dst = load_idx(ei32, e + E, idx64);
    int pos = atomicAdd(&cur[dst], 1);
    esrc[rowptr[dst] + pos] = src;
}

// ---------------------------------------------------------------------------
// Gather-based mean aggregation: warp per node, lane owns one float4.
// ---------------------------------------------------------------------------
__global__ __launch_bounds__(256) void agg_gather_kernel(
    const int* __restrict__ rowptr, const int* __restrict__ esrc,
    const float4* __restrict__ x4, float4* __restrict__ out4,
    const float* __restrict__ deg, int Nn) {
    int w = (blockIdx.x * blockDim.x + threadIdx.x) >> 5;
    if (w >= Nn) return;
    int lane = threadIdx.x & 31;
    int s = rowptr[w];
    int t = rowptr[w + 1];
    float4 a = make_float4(0.f, 0.f, 0.f, 0.f);
    int j = s;
    for (; j + 4 <= t; j += 4) {
        int s0 = esrc[j];
        int s1 = esrc[j + 1];
        int s2 = esrc[j + 2];
        int s3 = esrc[j + 3];
        float4 v0 = x4[(long long)s0 * 32 + lane];
        float4 v1 = x4[(long long)s1 * 32 + lane];
        float4 v2 = x4[(long long)s2 * 32 + lane];
        float4 v3 = x4[(long long)s3 * 32 + lane];
        a.x += (v0.x + v1.x) + (v2.x + v3.x);
        a.y += (v0.y + v1.y) + (v2.y + v3.y);
        a.z += (v0.z + v1.z) + (v2.z + v3.z);
        a.w += (v0.w + v1.w) + (v2.w + v3.w);
    }
    for (; j < t; j++) {
        int s0 = esrc[j];
        float4 v = x4[(long long)s0 * 32 + lane];
        a.x += v.x;
        a.y += v.y;
        a.z += v.z;
        a.w += v.w;
    }
    float rd = 1.0f / deg[w];
    a.x *= rd;
    a.y *= rd;
    a.z *= rd;
    a.w *= rd;
    out4[(long long)w * 32 + lane] = a;
}

// ---------------------------------------------------------------------------
// Weights -> bf16 hi/lo, row-major [ch][j][k].
// ch0: A = s0*W_self + s2*W_hp ; ch1: B = s1*W_nb1 - s2*W_hp ; ch2: C = s3*W_nb2
// ---------------------------------------------------------------------------
__global__ void weight_combine_kernel(const float* __restrict__ Wself,
                                      const float* __restrict__ Wnb1,
                                      const float* __restrict__ Whp,
                                      const float* __restrict__ Wnb2,
                                      const float* __restrict__ logits,
                                      __nv_bfloat16* __restrict__ Wh,
                                      __nv_bfloat16* __restrict__ Wl) {
    __shared__ float s[4];
    if (threadIdx.x < 4) s[threadIdx.x] = 2.0f / (1.0f + expf(-logits[threadIdx.x]));
    __syncthreads();
    for (int idx = blockIdx.x * blockDim.x + threadIdx.x; idx < DF * DF;
         idx += gridDim.x * blockDim.x) {
        float vals[3];
        vals[0] = s[0] * Wself[idx] + s[2] * Whp[idx];
        vals[1] = s[1] * Wnb1[idx] - s[2] * Whp[idx];
        vals[2] = s[3] * Wnb2[idx];
        for (int ch = 0; ch < 3; ch++) {
            float v = vals[ch];
            __nv_bfloat16 hi = __float2bfloat16_rn(v);
            __nv_bfloat16 lo = __float2bfloat16_rn(v - __bfloat162float(hi));
            Wh[ch * 16384 + idx] = hi;
            Wl[ch * 16384 + idx] = lo;
        }
    }
}

// ---------------------------------------------------------------------------
// WMMA GEMM (CTA: 64 rows x 128 cols, K=384 as 3 chunks of 128) + bias + LN.
// 3-term bf16 split: Xh*Wh + Xh*Wl + Xl*Wh, fp32 accumulators.
// 8 warps; warp tile 32x32 (2x2 of 16x16 fragments).
// W chunk staged to smem (coalesced uint4) -> fragment loads are LDS, not
// scalar LDG.U16. smem = 100 KB, __launch_bounds__(256,2) -> 2 CTAs/SM.
// ---------------------------------------------------------------------------
#define BMR 64    // CTA rows
#define LDX 144   // bf16 elements per row in X stage (288B rows, 32B aligned)
#define LDZ 132   // floats per row in Z epilogue tile

__global__ __launch_bounds__(256, 2) void wmma_gemm_ln_kernel(
    const float* __restrict__ h, const float* __restrict__ nb1,
    const float* __restrict__ nb2,
    const __nv_bfloat16* __restrict__ Wh,
    const __nv_bfloat16* __restrict__ Wl,
    const float* __restrict__ bias, const float* __restrict__ gamma,
    const float* __restrict__ beta, float* __restrict__ out, int Nn) {
    extern __shared__ __align__(32) char sm[];
    __nv_bfloat16* Xh_s = (__nv_bfloat16*)sm;                 // 64*144*2 = 18,432
    __nv_bfloat16* Xl_s = (__nv_bfloat16*)(sm + 18432);       // 18,432
    __nv_bfloat16* Wh_s = (__nv_bfloat16*)(sm + 36864);       // 128*128*2 = 32,768
    __nv_bfloat16* Wl_s = (__nv_bfloat16*)(sm + 69632);       // 32,768 (total 102,400)
    float* Z = (float*)sm;                                    // 64*132*4 = 33,792 (aliases X)

    __shared__ float bias_s[128];
    __shared__ float gamma_s[128];
    __shared__ float beta_s[128];
    __shared__ float mean_s[BMR];
    __shared__ float inv_s[BMR];

    int tid = threadIdx.x;
    int wid = tid >> 5;
    int row0 = blockIdx.x * BMR;
    int warp_row = wid >> 2;        // 0..1 -> rows warp_row*32
    int warp_col = wid & 3;         // 0..3 -> cols warp_col*32

    if (tid < 128) {
        bias_s[tid] = bias[tid];
        gamma_s[tid] = gamma[tid];
        beta_s[tid] = beta[tid];
    }

    wmma::fragment<wmma::accumulator, 16, 16, 16, float> acc[2][2];
    for (int i = 0; i < 2; i++)
        for (int j = 0; j < 2; j++)
            wmma::fill_fragment(acc[i][j], 0.0f);

    const float* srcs[3];
    srcs[0] = h;
    srcs[1] = nb1;
    srcs[2] = nb2;

    for (int ch = 0; ch < 3; ch++) {
        const float* S = srcs[ch];
        __syncthreads();   // previous chunk's consumers done before overwrite

        // Stage X: 64 rows x 128 cols fp32 -> bf16 hi/lo (2048 float4 loads).
        for (int it = 0; it < 8; it++) {
            int idx = it * 256 + tid;
            int row = idx >> 5;
            int col = (idx & 31) * 4;
            float4 v = make_float4(0.f, 0.f, 0.f, 0.f);
            int gr = row0 + row;
            if (gr < Nn) v = *(const float4*)(S + (long long)gr * DF + col);
            __nv_bfloat16 hx = __float2bfloat16_rn(v.x);
            __nv_bfloat16 hy = __float2bfloat16_rn(v.y);
            __nv_bfloat16 hz = __float2bfloat16_rn(v.z);
            __nv_bfloat16 hw = __float2bfloat16_rn(v.w);
            __nv_bfloat16 lx = __float2bfloat16_rn(v.x - __bfloat162float(hx));
            __nv_bfloat16 ly = __float2bfloat16_rn(v.y - __bfloat162float(hy));
            __nv_bfloat16 lz = __float2bfloat16_rn(v.z - __bfloat162float(hz));
            __nv_bfloat16 lw = __float2bfloat16_rn(v.w - __bfloat162float(hw));
            uint2 hv;
            uint2 lv;
            hv.x = (unsigned)__bfloat16_as_ushort(hx)
                 | ((unsigned)__bfloat16_as_ushort(hy) << 16);
            hv.y = (unsigned)__bfloat16_as_ushort(hz)
                 | ((unsigned)__bfloat16_as_ushort(hw) << 16);
            lv.x = (unsigned)__bfloat16_as_ushort(lx)
                 | ((unsigned)__bfloat16_as_ushort(ly) << 16);
            lv.y = (unsigned)__bfloat16_as_ushort(lz)
                 | ((unsigned)__bfloat16_as_ushort(lw) << 16);
            *(uint2*)(Xh_s + row * LDX + col) = hv;
            *(uint2*)(Xl_s + row * LDX + col) = lv;
        }
        // Stage W chunk hi/lo: 2 x 32 KB, coalesced uint4 copies.
        {
            const uint4* whs = (const uint4*)(Wh + ch * 16384);
            const uint4* wls = (const uint4*)(Wl + ch * 16384);
            uint4* whd = (uint4*)Wh_s;
            uint4* wld = (uint4*)Wl_s;
            for (int it = 0; it < 8; it++) {
                whd[it * 256 + tid] = whs[it * 256 + tid];
                wld[it * 256 + tid] = wls[it * 256 + tid];
            }
        }
        __syncthreads();

        // MMA over this chunk's K=128; all fragment loads from smem.
        for (int ks = 0; ks < 8; ks++) {
            int k0 = ks * 16;
            wmma::fragment<wmma::matrix_a, 16, 16, 16, __nv_bfloat16, wmma::row_major> ah[2], al[2];
            for (int i = 0; i < 2; i++) {
                int r = warp_row * 32 + i * 16;
                wmma::load_matrix_sync(ah[i], Xh_s + r * LDX + k0, LDX);
                wmma::load_matrix_sync(al[i], Xl_s + r * LDX + k0, LDX);
            }
            for (int j = 0; j < 2; j++) {
                int c = warp_col * 32 + j * 16;
                wmma::fragment<wmma::matrix_b, 16, 16, 16, __nv_bfloat16, wmma::col_major> bh, bl;
                wmma::load_matrix_sync(bh, Wh_s + c * 128 + k0, 128);
                wmma::load_matrix_sync(bl, Wl_s + c * 128 + k0, 128);
                for (int i = 0; i < 2; i++) {
                    wmma::mma_sync(acc[i][j], ah[i], bh, acc[i][j]);
                    wmma::mma_sync(acc[i][j], ah[i], bl, acc[i][j]);
                    wmma::mma_sync(acc[i][j], al[i], bh, acc[i][j]);
                }
            }
        }
    }
    __syncthreads();   // all MMA consumers done; Z aliases X stage

    // Store accumulators to Z
    for (int i = 0; i < 2; i++) {
        for (int j = 0; j < 2; j++) {
            int r = warp_row * 32 + i * 16;
            int c = warp_col * 32 + j * 16;
            wmma::store_matrix_sync(Z + r * LDZ + c, acc[i][j], LDZ, wmma::mem_row_major);
        }
    }
    __syncthreads();

    // LayerNorm stats: 4 threads per row, 32 cols each; add bias in-place.
    {
        int row = tid >> 2;
        int q = tid & 3;
        float sum = 0.f;
        float sq = 0.f;
        for (int c = 0; c < 32; c++) {
            int col = q * 32 + c;
            float z = Z[row * LDZ + col] + bias_s[col];
            Z[row * LDZ + col] = z;
            sum += z;
            sq += z * z;
        }
        sum += __shfl_xor_sync(0xffffffffu, sum, 1);
        sq += __shfl_xor_sync(0xffffffffu, sq, 1);
        sum += __shfl_xor_sync(0xffffffffu, sum, 2);
        sq += __shfl_xor_sync(0xffffffffu, sq, 2);
        if (q == 0) {
            float mean = sum * (1.0f / 128.0f);
            float var = sq * (1.0f / 128.0f) - mean * mean;
            mean_s[row] = mean;
            inv_s[row] = rsqrtf(var + 1e-5f);
        }
    }
    __syncthreads();

    // Coalesced normalize + store: 8 iters x 256 threads x float4
    for (int it = 0; it < 8; it++) {
        int g = it * 1024 + tid * 4;
        int row = g >> 7;
        int col = g & 127;
        int gr = row0 + row;
        if (gr < Nn) {
            float m = mean_s[row];
            float iv = inv_s[row];
            float4 o;
            o.x = (Z[row * LDZ + col + 0] - m) * iv * gamma_s[col + 0] + beta_s[col + 0];
            o.y = (Z[row * LDZ + col + 1] - m) * iv * gamma_s[col + 1] + beta_s[col + 1];
            o.z = (Z[row * LDZ + col + 2] - m) * iv * gamma_s[col + 2] + beta_s[col + 2];
            o.w = (Z[row * LDZ + col + 3] - m) * iv * gamma_s[col + 3] + beta_s[col + 3];
            *(float4*)(out + (long long)gr * DF + col) = o;
        }
    }
}

// ---------------------------------------------------------------------------
// Launch
// ---------------------------------------------------------------------------
extern "C" void kernel_launch(void* const* d_in, const int* in_sizes, int n_in,
                              void* d_out, int out_size) {
    const float* h      = (const float*)d_in[0];
    const int*   ei32   = (const int*)d_in[1];
    const float* deg    = (const float*)d_in[2];
    const float* Wself  = (const float*)d_in[3];
    const float* Wnb1   = (const float*)d_in[4];
    const float* Whp    = (const float*)d_in[5];
    const float* Wnb2   = (const float*)d_in[6];
    const float* bias   = (const float*)d_in[7];
    const float* logits = (const float*)d_in[8];
    const float* gamma  = (const float*)d_in[9];
    const float* beta   = (const float*)d_in[10];
    float*       out    = (float*)d_out;

    int Nn = in_sizes[2];
    long long E = in_sizes[1] / 2;

    float* agg1;
    float* agg2;
    __nv_bfloat16* Wh;
    __nv_bfloat16* Wl;
    int* cnt;
    int* scan;
    int* bsum;
    int* rowptr;
    int* esrc;
    cudaGetSymbolAddress((void**)&agg1, g_agg1);
    cudaGetSymbolAddress((void**)&agg2, g_agg2);
    cudaGetSymbolAddress((void**)&Wh, g_Wh);
    cudaGetSymbolAddress((void**)&Wl, g_Wl);
    cudaGetSymbolAddress((void**)&cnt, g_cnt);
    cudaGetSymbolAddress((void**)&scan, g_scan);
    cudaGetSymbolAddress((void**)&bsum, g_bsum);
    cudaGetSymbolAddress((void**)&rowptr, g_rowptr);
    cudaGetSymbolAddress((void**)&esrc, g_esrc);

    const int T = 256;
    int nb_nodes = (Nn + T - 1) / T;
    int nb_edges = (int)((E + T - 1) / T);
    int nb_scan  = (Nn + SCAN_B - 1) / SCAN_B;
    int nb_agg   = (Nn * 32 + T - 1) / T;
    int fb       = (Nn + BMR - 1) / BMR;
    const int GEMM_SMEM = 102400;  // Xh+Xl (36,864) + Wh+Wl (65,536)

    cudaFuncSetAttribute(wmma_gemm_ln_kernel,
                         cudaFuncAttributeMaxDynamicSharedMemorySize, GEMM_SMEM);

    detect_idx_kernel<<<1, 32>>>((const unsigned*)ei32);
    cnt_zero_kernel<<<nb_nodes, T>>>(cnt, Nn);
    hist_kernel<<<nb_edges, T>>>(ei32, cnt, E);
    scan_a_kernel<<<nb_scan, SCAN_B>>>(cnt, scan, bsum, Nn);
    scan_b_kernel<<<1, 1024>>>(bsum, nb_scan);
    scan_c_kernel<<<nb_nodes, T>>>(scan, bsum, rowptr, cnt, Nn);
    fill_kernel<<<nb_edges, T>>>(ei32, rowptr, cnt, esrc, E);
    weight_combine_kernel<<<64, T>>>(Wself, Wnb1, Whp, Wnb2, logits, Wh, Wl);
    agg_gather_kernel<<<nb_agg, T>>>(rowptr, esrc, (const float4*)h,
                                     (float4*)agg1, deg, Nn);
    agg_gather_kernel<<<nb_agg, T>>>(rowptr, esrc, (const float4*)agg1,
                                     (float4*)agg2, deg, Nn);
    wmma_gemm_ln_kernel<<<fb, 256, GEMM_SMEM>>>(h, agg1, agg2, Wh, Wl,
                                                bias, gamma, beta, out, Nn);
}

// round 10
// speedup vs baseline: 1.1265x; 1.1265x over previous
#include <cuda_runtime.h>
#include <cuda_bf16.h>
#include <mma.h>
#include <math.h>

using namespace nvcuda;

#define NMAX 100000
#define EMAX 1600000
#define DF   128
#define SCAN_B 1024

// Scratch (__device__ globals; allocation is forbidden).
__device__ float g_agg1[(size_t)NMAX * DF];
__device__ float g_agg2[(size_t)NMAX * DF];
__device__ __align__(16) __nv_bfloat16 g_Wh[3 * 16384];  // row-major [ch][j][k] hi
__device__ __align__(16) __nv_bfloat16 g_Wl[3 * 16384];  // row-major [ch][j][k] lo
__device__ int   g_idx64;
__device__ int   g_cnt[NMAX];
__device__ int   g_scan[NMAX];
__device__ int   g_bsum[1024];
__device__ int   g_rowptr[NMAX + 1];
__device__ int   g_esrc[EMAX];

// ---------------------------------------------------------------------------
// Edge-index dtype detection
// ---------------------------------------------------------------------------
__global__ void detect_idx_kernel(const unsigned* __restrict__ ei_raw) {
    if (threadIdx.x == 0 && blockIdx.x == 0) {
        unsigned acc = 0;
        for (int i = 0; i < 64; i++) acc |= ei_raw[2 * i + 1];
        g_idx64 = (acc == 0u) ? 1 : 0;
    }
}

__device__ __forceinline__ int load_idx(const int* __restrict__ ei32,
                                        long long pos, int idx64) {
    return idx64 ? ei32[2 * pos] : ei32[pos];
}

// ---------------------------------------------------------------------------
// CSR build
// ---------------------------------------------------------------------------
__global__ void cnt_zero_kernel(int* __restrict__ cnt, int n) {
    int i = blockIdx.x * blockDim.x + threadIdx.x;
    if (i < n) cnt[i] = 0;
}

__global__ void hist_kernel(const int* __restrict__ ei32, int* __restrict__ cnt,
                            long long E) {
    long long e = (long long)blockIdx.x * blockDim.x + threadIdx.x;
    if (e >= E) return;
    int dst = load_idx(ei32, e + E, g_idx64);
    atomicAdd(&cnt[dst], 1);
}

__global__ void scan_a_kernel(const int* __restrict__ cnt, int* __restrict__ scan,
                              int* __restrict__ bsum, int n) {
    __shared__ int sh[SCAN_B];
    int tid = threadIdx.x;
    int i = blockIdx.x * SCAN_B + tid;
    sh[tid] = (i < n) ? cnt[i] : 0;
    __syncthreads();
    for (int o = 1; o < SCAN_B; o <<= 1) {
        int t = (tid >= o) ? sh[tid - o] : 0;
        __syncthreads();
        if (tid >= o) sh[tid] += t;
        __syncthreads();
    }
    if (i < n) scan[i] = sh[tid];
    if (tid == SCAN_B - 1) bsum[blockIdx.x] = sh[tid];
}

__global__ void scan_b_kernel(int* __restrict__ bsum, int nb) {
    __shared__ int sh[1024];
    int tid = threadIdx.x;
    int v = (tid < nb) ? bsum[tid] : 0;
    sh[tid] = v;
    __syncthreads();
    for (int o = 1; o < 1024; o <<= 1) {
        int t = (tid >= o) ? sh[tid - o] : 0;
        __syncthreads();
        if (tid >= o) sh[tid] += t;
        __syncthreads();
    }
    if (tid < nb) bsum[tid] = sh[tid] - v;
}

__global__ void scan_c_kernel(const int* __restrict__ scan,
                              const int* __restrict__ bsum,
                              int* __restrict__ rowptr, int* __restrict__ cnt, int n) {
    int i = blockIdx.x * blockDim.x + threadIdx.x;
    if (i < n) {
        rowptr[i + 1] = scan[i] + bsum[i / SCAN_B];
        cnt[i] = 0;
    }
    if (i == 0) rowptr[0] = 0;
}

__global__ void fill_kernel(const int* __restrict__ ei32,
                            const int* __restrict__ rowptr,
                            int* __restrict__ cur, int* __restrict__ esrc,
                            long long E) {
    long long e = (long long)blockIdx.x * blockDim.x + threadIdx.x;
    if (e >= E) return;
    int idx64 = g_idx64;
    int src = load_idx(ei32, e, idx64);
    int dst = load_idx(ei32, e + E, idx64);
    int pos = atomicAdd(&cur[dst], 1);
    esrc[rowptr[dst] + pos] = src;
}

// ---------------------------------------------------------------------------
// Gather-based mean aggregation: warp per node, lane owns one float4.
// 8-deep unroll -> 8 outstanding LDG.128 per warp (cover L2 latency).
// ---------------------------------------------------------------------------
__global__ __launch_bounds__(256) void agg_gather_kernel(
    const int* __restrict__ rowptr, const int* __restrict__ esrc,
    const float4* __restrict__ x4, float4* __restrict__ out4,
    const float* __restrict__ deg, int Nn) {
    int w = (blockIdx.x * blockDim.x + threadIdx.x) >> 5;
    if (w >= Nn) return;
    int lane = threadIdx.x & 31;
    int s = rowptr[w];
    int t = rowptr[w + 1];
    float4 a = make_float4(0.f, 0.f, 0.f, 0.f);
    int j = s;
    for (; j + 8 <= t; j += 8) {
        int si[8];
#pragma unroll
        for (int u = 0; u < 8; u++) si[u] = esrc[j + u];
        float4 v[8];
#pragma unroll
        for (int u = 0; u < 8; u++) v[u] = x4[(long long)si[u] * 32 + lane];
        float4 p0, p1;
        p0.x = (v[0].x + v[1].x) + (v[2].x + v[3].x);
        p0.y = (v[0].y + v[1].y) + (v[2].y + v[3].y);
        p0.z = (v[0].z + v[1].z) + (v[2].z + v[3].z);
        p0.w = (v[0].w + v[1].w) + (v[2].w + v[3].w);
        p1.x = (v[4].x + v[5].x) + (v[6].x + v[7].x);
        p1.y = (v[4].y + v[5].y) + (v[6].y + v[7].y);
        p1.z = (v[4].z + v[5].z) + (v[6].z + v[7].z);
        p1.w = (v[4].w + v[5].w) + (v[6].w + v[7].w);
        a.x += p0.x + p1.x;
        a.y += p0.y + p1.y;
        a.z += p0.z + p1.z;
        a.w += p0.w + p1.w;
    }
    for (; j < t; j++) {
        int s0 = esrc[j];
        float4 v = x4[(long long)s0 * 32 + lane];
        a.x += v.x;
        a.y += v.y;
        a.z += v.z;
        a.w += v.w;
    }
    float rd = 1.0f / deg[w];
    a.x *= rd;
    a.y *= rd;
    a.z *= rd;
    a.w *= rd;
    out4[(long long)w * 32 + lane] = a;
}

// ---------------------------------------------------------------------------
// Weights -> bf16 hi/lo, row-major [ch][j][k].
// ch0: A = s0*W_self + s2*W_hp ; ch1: B = s1*W_nb1 - s2*W_hp ; ch2: C = s3*W_nb2
// ---------------------------------------------------------------------------
__global__ void weight_combine_kernel(const float* __restrict__ Wself,
                                      const float* __restrict__ Wnb1,
                                      const float* __restrict__ Whp,
                                      const float* __restrict__ Wnb2,
                                      const float* __restrict__ logits,
                                      __nv_bfloat16* __restrict__ Wh,
                                      __nv_bfloat16* __restrict__ Wl) {
    __shared__ float s[4];
    if (threadIdx.x < 4) s[threadIdx.x] = 2.0f / (1.0f + expf(-logits[threadIdx.x]));
    __syncthreads();
    for (int idx = blockIdx.x * blockDim.x + threadIdx.x; idx < DF * DF;
         idx += gridDim.x * blockDim.x) {
        float vals[3];
        vals[0] = s[0] * Wself[idx] + s[2] * Whp[idx];
        vals[1] = s[1] * Wnb1[idx] - s[2] * Whp[idx];
        vals[2] = s[3] * Wnb2[idx];
        for (int ch = 0; ch < 3; ch++) {
            float v = vals[ch];
            __nv_bfloat16 hi = __float2bfloat16_rn(v);
            __nv_bfloat16 lo = __float2bfloat16_rn(v - __bfloat162float(hi));
            Wh[ch * 16384 + idx] = hi;
            Wl[ch * 16384 + idx] = lo;
        }
    }
}

// ---------------------------------------------------------------------------
// WMMA GEMM (CTA: 64 rows x 128 cols, K=384 as 3 chunks of 128) + bias + LN.
// 3-term bf16 split: Xh*Wh + Xh*Wl + Xl*Wh, fp32 accumulators.
// 8 warps; warp tile 32x32 (2x2 of 16x16 fragments). B loaded from GLOBAL
// (W images are L1/L2-resident) -> no W smem copy, smem = 36,864 B,
// ~110 regs/thread -> 2 CTAs/SM.  [round-8 config: fastest measured]
// ---------------------------------------------------------------------------
#define BMR 64    // CTA rows
#define LDX 144   // bf16 elements per row in X stage (288B rows, 32B aligned)
#define LDZ 132   // floats per row in Z epilogue tile

__global__ __launch_bounds__(256) void wmma_gemm_ln_kernel(
    const float* __restrict__ h, const float* __restrict__ nb1,
    const float* __restrict__ nb2,
    const __nv_bfloat16* __restrict__ Wh,
    const __nv_bfloat16* __restrict__ Wl,
    const float* __restrict__ bias, const float* __restrict__ gamma,
    const float* __restrict__ beta, float* __restrict__ out, int Nn) {
    extern __shared__ __align__(32) char sm[];
    __nv_bfloat16* Xh_s = (__nv_bfloat16*)sm;                 // 64*144*2 = 18,432
    __nv_bfloat16* Xl_s = (__nv_bfloat16*)(sm + 18432);       // 18,432 (total 36,864)
    float* Z = (float*)sm;                                    // 64*132*4 = 33,792 (aliases X)

    __shared__ float bias_s[128];
    __shared__ float gamma_s[128];
    __shared__ float beta_s[128];
    __shared__ float mean_s[BMR];
    __shared__ float inv_s[BMR];

    int tid = threadIdx.x;
    int wid = tid >> 5;
    int row0 = blockIdx.x * BMR;
    int warp_row = wid >> 2;        // 0..1 -> rows warp_row*32
    int warp_col = wid & 3;         // 0..3 -> cols warp_col*32

    if (tid < 128) {
        bias_s[tid] = bias[tid];
        gamma_s[tid] = gamma[tid];
        beta_s[tid] = beta[tid];
    }

    wmma::fragment<wmma::accumulator, 16, 16, 16, float> acc[2][2];
    for (int i = 0; i < 2; i++)
        for (int j = 0; j < 2; j++)
            wmma::fill_fragment(acc[i][j], 0.0f);

    const float* srcs[3];
    srcs[0] = h;
    srcs[1] = nb1;
    srcs[2] = nb2;

    for (int ch = 0; ch < 3; ch++) {
        const float* S = srcs[ch];
        const __nv_bfloat16* WhC = Wh + ch * 16384;
        const __nv_bfloat16* WlC = Wl + ch * 16384;
        __syncthreads();   // previous chunk's consumers done before overwrite

        // Stage X: 64 rows x 128 cols fp32 -> bf16 hi/lo (2048 float4 loads).
        for (int it = 0; it < 8; it++) {
            int idx = it * 256 + tid;
            int row = idx >> 5;
            int col = (idx & 31) * 4;
            float4 v = make_float4(0.f, 0.f, 0.f, 0.f);
            int gr = row0 + row;
            if (gr < Nn) v = *(const float4*)(S + (long long)gr * DF + col);
            __nv_bfloat16 hx = __float2bfloat16_rn(v.x);
            __nv_bfloat16 hy = __float2bfloat16_rn(v.y);
            __nv_bfloat16 hz = __float2bfloat16_rn(v.z);
            __nv_bfloat16 hw = __float2bfloat16_rn(v.w);
            __nv_bfloat16 lx = __float2bfloat16_rn(v.x - __bfloat162float(hx));
            __nv_bfloat16 ly = __float2bfloat16_rn(v.y - __bfloat162float(hy));
            __nv_bfloat16 lz = __float2bfloat16_rn(v.z - __bfloat162float(hz));
            __nv_bfloat16 lw = __float2bfloat16_rn(v.w - __bfloat162float(hw));
            uint2 hv;
            uint2 lv;
            hv.x = (unsigned)__bfloat16_as_ushort(hx)
                 | ((unsigned)__bfloat16_as_ushort(hy) << 16);
            hv.y = (unsigned)__bfloat16_as_ushort(hz)
                 | ((unsigned)__bfloat16_as_ushort(hw) << 16);
            lv.x = (unsigned)__bfloat16_as_ushort(lx)
                 | ((unsigned)__bfloat16_as_ushort(ly) << 16);
            lv.y = (unsigned)__bfloat16_as_ushort(lz)
                 | ((unsigned)__bfloat16_as_ushort(lw) << 16);
            *(uint2*)(Xh_s + row * LDX + col) = hv;
            *(uint2*)(Xl_s + row * LDX + col) = lv;
        }
        __syncthreads();

        // MMA over this chunk's K=128. B fragments read straight from global.
        for (int ks = 0; ks < 8; ks++) {
            int k0 = ks * 16;
            wmma::fragment<wmma::matrix_a, 16, 16, 16, __nv_bfloat16, wmma::row_major> ah[2], al[2];
            for (int i = 0; i < 2; i++) {
                int r = warp_row * 32 + i * 16;
                wmma::load_matrix_sync(ah[i], Xh_s + r * LDX + k0, LDX);
                wmma::load_matrix_sync(al[i], Xl_s + r * LDX + k0, LDX);
            }
            for (int j = 0; j < 2; j++) {
                int c = warp_col * 32 + j * 16;
                wmma::fragment<wmma::matrix_b, 16, 16, 16, __nv_bfloat16, wmma::col_major> bh, bl;
                wmma::load_matrix_sync(bh, WhC + c * 128 + k0, 128);
                wmma::load_matrix_sync(bl, WlC + c * 128 + k0, 128);
                for (int i = 0; i < 2; i++) {
                    wmma::mma_sync(acc[i][j], ah[i], bh, acc[i][j]);
                    wmma::mma_sync(acc[i][j], ah[i], bl, acc[i][j]);
                    wmma::mma_sync(acc[i][j], al[i], bh, acc[i][j]);
                }
            }
        }
    }
    __syncthreads();   // all MMA consumers done; Z aliases X stage

    // Store accumulators to Z
    for (int i = 0; i < 2; i++) {
        for (int j = 0; j < 2; j++) {
            int r = warp_row * 32 + i * 16;
            int c = warp_col * 32 + j * 16;
            wmma::store_matrix_sync(Z + r * LDZ + c, acc[i][j], LDZ, wmma::mem_row_major);
        }
    }
    __syncthreads();

    // LayerNorm stats: 4 threads per row, 32 cols each; add bias in-place.
    {
        int row = tid >> 2;
        int q = tid & 3;
        float sum = 0.f;
        float sq = 0.f;
        for (int c = 0; c < 32; c++) {
            int col = q * 32 + c;
            float z = Z[row * LDZ + col] + bias_s[col];
            Z[row * LDZ + col] = z;
            sum += z;
            sq += z * z;
        }
        sum += __shfl_xor_sync(0xffffffffu, sum, 1);
        sq += __shfl_xor_sync(0xffffffffu, sq, 1);
        sum += __shfl_xor_sync(0xffffffffu, sum, 2);
        sq += __shfl_xor_sync(0xffffffffu, sq, 2);
        if (q == 0) {
            float mean = sum * (1.0f / 128.0f);
            float var = sq * (1.0f / 128.0f) - mean * mean;
            mean_s[row] = mean;
            inv_s[row] = rsqrtf(var + 1e-5f);
        }
    }
    __syncthreads();

    // Coalesced normalize + store: 8 iters x 256 threads x float4
    for (int it = 0; it < 8; it++) {
        int g = it * 1024 + tid * 4;
        int row = g >> 7;
        int col = g & 127;
        int gr = row0 + row;
        if (gr < Nn) {
            float m = mean_s[row];
            float iv = inv_s[row];
            float4 o;
            o.x = (Z[row * LDZ + col + 0] - m) * iv * gamma_s[col + 0] + beta_s[col + 0];
            o.y = (Z[row * LDZ + col + 1] - m) * iv * gamma_s[col + 1] + beta_s[col + 1];
            o.z = (Z[row * LDZ + col + 2] - m) * iv * gamma_s[col + 2] + beta_s[col + 2];
            o.w = (Z[row * LDZ + col + 3] - m) * iv * gamma_s[col + 3] + beta_s[col + 3];
            *(float4*)(out + (long long)gr * DF + col) = o;
        }
    }
}

// ---------------------------------------------------------------------------
// Launch
// ---------------------------------------------------------------------------
extern "C" void kernel_launch(void* const* d_in, const int* in_sizes, int n_in,
                              void* d_out, int out_size) {
    const float* h      = (const float*)d_in[0];
    const int*   ei32   = (const int*)d_in[1];
    const float* deg    = (const float*)d_in[2];
    const float* Wself  = (const float*)d_in[3];
    const float* Wnb1   = (const float*)d_in[4];
    const float* Whp    = (const float*)d_in[5];
    const float* Wnb2   = (const float*)d_in[6];
    const float* bias   = (const float*)d_in[7];
    const float* logits = (const float*)d_in[8];
    const float* gamma  = (const float*)d_in[9];
    const float* beta   = (const float*)d_in[10];
    float*       out    = (float*)d_out;

    int Nn = in_sizes[2];
    long long E = in_sizes[1] / 2;

    float* agg1;
    float* agg2;
    __nv_bfloat16* Wh;
    __nv_bfloat16* Wl;
    int* cnt;
    int* scan;
    int* bsum;
    int* rowptr;
    int* esrc;
    cudaGetSymbolAddress((void**)&agg1, g_agg1);
    cudaGetSymbolAddress((void**)&agg2, g_agg2);
    cudaGetSymbolAddress((void**)&Wh, g_Wh);
    cudaGetSymbolAddress((void**)&Wl, g_Wl);
    cudaGetSymbolAddress((void**)&cnt, g_cnt);
    cudaGetSymbolAddress((void**)&scan, g_scan);
    cudaGetSymbolAddress((void**)&bsum, g_bsum);
    cudaGetSymbolAddress((void**)&rowptr, g_rowptr);
    cudaGetSymbolAddress((void**)&esrc, g_esrc);

    const int T = 256;
    int nb_nodes = (Nn + T - 1) / T;
    int nb_edges = (int)((E + T - 1) / T);
    int nb_scan  = (Nn + SCAN_B - 1) / SCAN_B;
    int nb_agg   = (Nn * 32 + T - 1) / T;
    int fb       = (Nn + BMR - 1) / BMR;
    const int GEMM_SMEM = 36864;   // Xh + Xl stage (Z epilogue aliases it)

    cudaFuncSetAttribute(wmma_gemm_ln_kernel,
                         cudaFuncAttributeMaxDynamicSharedMemorySize, GEMM_SMEM);

    // Off critical path first
    weight_combine_kernel<<<64, T>>>(Wself, Wnb1, Whp, Wnb2, logits, Wh, Wl);
    detect_idx_kernel<<<1, 32>>>((const unsigned*)ei32);
    // CSR build
    cnt_zero_kernel<<<nb_nodes, T>>>(cnt, Nn);
    hist_kernel<<<nb_edges, T>>>(ei32, cnt, E);
    scan_a_kernel<<<nb_scan, SCAN_B>>>(cnt, scan, bsum, Nn);
    scan_b_kernel<<<1, 1024>>>(bsum, nb_scan);
    scan_c_kernel<<<nb_nodes, T>>>(scan, bsum, rowptr, cnt, Nn);
    fill_kernel<<<nb_edges, T>>>(ei32, rowptr, cnt, esrc, E);
    // Aggregations
    agg_gather_kernel<<<nb_agg, T>>>(rowptr, esrc, (const float4*)h,
                                     (float4*)agg1, deg, Nn);
    agg_gather_kernel<<<nb_agg, T>>>(rowptr, esrc, (const float4*)agg1,
                                     (float4*)agg2, deg, Nn);
    // Fused GEMM + bias + LayerNorm
    wmma_gemm_ln_kernel<<<fb, 256, GEMM_SMEM>>>(h, agg1, agg2, Wh, Wl,
                                                bias, gamma, beta, out, Nn);
}

// round 11
// speedup vs baseline: 1.1614x; 1.0310x over previous
#include <cuda_runtime.h>
#include <cuda_bf16.h>
#include <mma.h>
#include <math.h>

using namespace nvcuda;

#define NMAX 100000
#define ESLOTS 1700000   // E + N slack (deg-derived counts over-allocate empty rows)
#define DF   128
#define SCAN_B 1024

// Scratch (__device__ globals; allocation is forbidden).
__device__ float g_agg1[(size_t)NMAX * DF];
__device__ float g_agg2[(size_t)NMAX * DF];
__device__ __align__(16) __nv_bfloat16 g_Wh[3 * 16384];  // row-major [ch][j][k] hi
__device__ __align__(16) __nv_bfloat16 g_Wl[3 * 16384];  // row-major [ch][j][k] lo
__device__ int   g_idx64;
__device__ int   g_cur[NMAX];        // fill cursor (starts at row base)
__device__ int   g_scan[NMAX];
__device__ int   g_bsum[1024];
__device__ int   g_rowptr[NMAX + 1]; // row base (from deg scan)
__device__ int   g_esrc[ESLOTS];

// ---------------------------------------------------------------------------
// Edge-index dtype detection
// ---------------------------------------------------------------------------
__global__ void detect_idx_kernel(const unsigned* __restrict__ ei_raw) {
    if (threadIdx.x == 0 && blockIdx.x == 0) {
        unsigned acc = 0;
        for (int i = 0; i < 64; i++) acc |= ei_raw[2 * i + 1];
        g_idx64 = (acc == 0u) ? 1 : 0;
    }
}

__device__ __forceinline__ int load_idx(const int* __restrict__ ei32,
                                        long long pos, int idx64) {
    return idx64 ? ei32[2 * pos] : ei32[pos];
}

// ---------------------------------------------------------------------------
// CSR build from deg (deg IS the clamped in-degree histogram -> no hist pass).
// ---------------------------------------------------------------------------
__global__ void scan_a_kernel(const float* __restrict__ deg, int* __restrict__ scan,
                              int* __restrict__ bsum, int n) {
    __shared__ int sh[SCAN_B];
    int tid = threadIdx.x;
    int i = blockIdx.x * SCAN_B + tid;
    sh[tid] = (i < n) ? (int)deg[i] : 0;
    __syncthreads();
    for (int o = 1; o < SCAN_B; o <<= 1) {
        int t = (tid >= o) ? sh[tid - o] : 0;
        __syncthreads();
        if (tid >= o) sh[tid] += t;
        __syncthreads();
    }
    if (i < n) scan[i] = sh[tid];
    if (tid == SCAN_B - 1) bsum[blockIdx.x] = sh[tid];
}

__global__ void scan_b_kernel(int* __restrict__ bsum, int nb) {
    __shared__ int sh[1024];
    int tid = threadIdx.x;
    int v = (tid < nb) ? bsum[tid] : 0;
    sh[tid] = v;
    __syncthreads();
    for (int o = 1; o < 1024; o <<= 1) {
        int t = (tid >= o) ? sh[tid - o] : 0;
        __syncthreads();
        if (tid >= o) sh[tid] += t;
        __syncthreads();
    }
    if (tid < nb) bsum[tid] = sh[tid] - v;
}

__global__ void scan_c_kernel(const int* __restrict__ scan,
                              const int* __restrict__ bsum,
                              const float* __restrict__ deg,
                              int* __restrict__ rowptr, int* __restrict__ cur, int n) {
    int i = blockIdx.x * blockDim.x + threadIdx.x;
    if (i < n) {
        int incl = scan[i] + bsum[i / SCAN_B];
        rowptr[i] = incl - (int)deg[i];   // row base (exclusive scan)
        cur[i] = incl - (int)deg[i];      // fill cursor starts at base
    }
}

__global__ void fill_kernel(const int* __restrict__ ei32,
                            int* __restrict__ cur, int* __restrict__ esrc,
                            long long E) {
    long long e = (long long)blockIdx.x * blockDim.x + threadIdx.x;
    if (e >= E) return;
    int idx64 = g_idx64;
    int src = load_idx(ei32, e, idx64);
    int dst = load_idx(ei32, e + E, idx64);
    int pos = atomicAdd(&cur[dst], 1);
    esrc[pos] = src;
}

// ---------------------------------------------------------------------------
// Gather-based mean aggregation: warp per node, lane owns one float4.
// Range = [rowptr[w], cur[w]) : cur is the post-fill cursor (= base + count).
// ---------------------------------------------------------------------------
__global__ __launch_bounds__(256) void agg_gather_kernel(
    const int* __restrict__ rowptr, const int* __restrict__ rowend,
    const int* __restrict__ esrc,
    const float4* __restrict__ x4, float4* __restrict__ out4,
    const float* __restrict__ deg, int Nn) {
    int w = (blockIdx.x * blockDim.x + threadIdx.x) >> 5;
    if (w >= Nn) return;
    int lane = threadIdx.x & 31;
    int s = rowptr[w];
    int t = rowend[w];
    float4 a = make_float4(0.f, 0.f, 0.f, 0.f);
    int j = s;
    for (; j + 8 <= t; j += 8) {
        int si[8];
#pragma unroll
        for (int u = 0; u < 8; u++) si[u] = esrc[j + u];
        float4 v[8];
#pragma unroll
        for (int u = 0; u < 8; u++) v[u] = x4[(long long)si[u] * 32 + lane];
        float4 p0, p1;
        p0.x = (v[0].x + v[1].x) + (v[2].x + v[3].x);
        p0.y = (v[0].y + v[1].y) + (v[2].y + v[3].y);
        p0.z = (v[0].z + v[1].z) + (v[2].z + v[3].z);
        p0.w = (v[0].w + v[1].w) + (v[2].w + v[3].w);
        p1.x = (v[4].x + v[5].x) + (v[6].x + v[7].x);
        p1.y = (v[4].y + v[5].y) + (v[6].y + v[7].y);
        p1.z = (v[4].z + v[5].z) + (v[6].z + v[7].z);
        p1.w = (v[4].w + v[5].w) + (v[6].w + v[7].w);
        a.x += p0.x + p1.x;
        a.y += p0.y + p1.y;
        a.z += p0.z + p1.z;
        a.w += p0.w + p1.w;
    }
    for (; j < t; j++) {
        int s0 = esrc[j];
        float4 v = x4[(long long)s0 * 32 + lane];
        a.x += v.x;
        a.y += v.y;
        a.z += v.z;
        a.w += v.w;
    }
    float rd = 1.0f / deg[w];
    a.x *= rd;
    a.y *= rd;
    a.z *= rd;
    a.w *= rd;
    out4[(long long)w * 32 + lane] = a;
}

// ---------------------------------------------------------------------------
// Weights -> bf16 hi/lo, row-major [ch][j][k].
// ch0: A = s0*W_self + s2*W_hp ; ch1: B = s1*W_nb1 - s2*W_hp ; ch2: C = s3*W_nb2
// ---------------------------------------------------------------------------
__global__ void weight_combine_kernel(const float* __restrict__ Wself,
                                      const float* __restrict__ Wnb1,
                                      const float* __restrict__ Whp,
                                      const float* __restrict__ Wnb2,
                                      const float* __restrict__ logits,
                                      __nv_bfloat16* __restrict__ Wh,
                                      __nv_bfloat16* __restrict__ Wl) {
    __shared__ float s[4];
    if (threadIdx.x < 4) s[threadIdx.x] = 2.0f / (1.0f + expf(-logits[threadIdx.x]));
    __syncthreads();
    for (int idx = blockIdx.x * blockDim.x + threadIdx.x; idx < DF * DF;
         idx += gridDim.x * blockDim.x) {
        float vals[3];
        vals[0] = s[0] * Wself[idx] + s[2] * Whp[idx];
        vals[1] = s[1] * Wnb1[idx] - s[2] * Whp[idx];
        vals[2] = s[3] * Wnb2[idx];
        for (int ch = 0; ch < 3; ch++) {
            float v = vals[ch];
            __nv_bfloat16 hi = __float2bfloat16_rn(v);
            __nv_bfloat16 lo = __float2bfloat16_rn(v - __bfloat162float(hi));
            Wh[ch * 16384 + idx] = hi;
            Wl[ch * 16384 + idx] = lo;
        }
    }
}

// ---------------------------------------------------------------------------
// WMMA GEMM (CTA: 64 rows x 128 cols, K=384 as 3 chunks of 128) + bias + LN.
// 3-term bf16 split: Xh*Wh + Xh*Wl + Xl*Wh, fp32 accumulators.
// 8 warps; warp tile 32x32 (2x2 of 16x16 fragments). B loaded from GLOBAL
// (W images are L1/L2-resident). smem = 36,864 B -> 2 CTAs/SM.
// ---------------------------------------------------------------------------
#define BMR 64    // CTA rows
#define LDX 144   // bf16 elements per row in X stage (288B rows, 32B aligned)
#define LDZ 132   // floats per row in Z epilogue tile

__global__ __launch_bounds__(256) void wmma_gemm_ln_kernel(
    const float* __restrict__ h, const float* __restrict__ nb1,
    const float* __restrict__ nb2,
    const __nv_bfloat16* __restrict__ Wh,
    const __nv_bfloat16* __restrict__ Wl,
    const float* __restrict__ bias, const float* __restrict__ gamma,
    const float* __restrict__ beta, float* __restrict__ out, int Nn) {
    extern __shared__ __align__(32) char sm[];
    __nv_bfloat16* Xh_s = (__nv_bfloat16*)sm;                 // 64*144*2 = 18,432
    __nv_bfloat16* Xl_s = (__nv_bfloat16*)(sm + 18432);       // 18,432 (total 36,864)
    float* Z = (float*)sm;                                    // 64*132*4 = 33,792 (aliases X)

    __shared__ float bias_s[128];
    __shared__ float gamma_s[128];
    __shared__ float beta_s[128];
    __shared__ float mean_s[BMR];
    __shared__ float inv_s[BMR];

    int tid = threadIdx.x;
    int wid = tid >> 5;
    int row0 = blockIdx.x * BMR;
    int warp_row = wid >> 2;        // 0..1 -> rows warp_row*32
    int warp_col = wid & 3;         // 0..3 -> cols warp_col*32

    if (tid < 128) {
        bias_s[tid] = bias[tid];
        gamma_s[tid] = gamma[tid];
        beta_s[tid] = beta[tid];
    }

    wmma::fragment<wmma::accumulator, 16, 16, 16, float> acc[2][2];
    for (int i = 0; i < 2; i++)
        for (int j = 0; j < 2; j++)
            wmma::fill_fragment(acc[i][j], 0.0f);

    const float* srcs[3];
    srcs[0] = h;
    srcs[1] = nb1;
    srcs[2] = nb2;

    for (int ch = 0; ch < 3; ch++) {
        const float* S = srcs[ch];
        const __nv_bfloat16* WhC = Wh + ch * 16384;
        const __nv_bfloat16* WlC = Wl + ch * 16384;
        __syncthreads();   // previous chunk's consumers done before overwrite

        // Stage X: 64 rows x 128 cols fp32 -> bf16 hi/lo (2048 float4 loads).
        for (int it = 0; it < 8; it++) {
            int idx = it * 256 + tid;
            int row = idx >> 5;
            int col = (idx & 31) * 4;
            float4 v = make_float4(0.f, 0.f, 0.f, 0.f);
            int gr = row0 + row;
            if (gr < Nn) v = *(const float4*)(S + (long long)gr * DF + col);
            __nv_bfloat16 hx = __float2bfloat16_rn(v.x);
            __nv_bfloat16 hy = __float2bfloat16_rn(v.y);
            __nv_bfloat16 hz = __float2bfloat16_rn(v.z);
            __nv_bfloat16 hw = __float2bfloat16_rn(v.w);
            __nv_bfloat16 lx = __float2bfloat16_rn(v.x - __bfloat162float(hx));
            __nv_bfloat16 ly = __float2bfloat16_rn(v.y - __bfloat162float(hy));
            __nv_bfloat16 lz = __float2bfloat16_rn(v.z - __bfloat162float(hz));
            __nv_bfloat16 lw = __float2bfloat16_rn(v.w - __bfloat162float(hw));
            uint2 hv;
            uint2 lv;
            hv.x = (unsigned)__bfloat16_as_ushort(hx)
                 | ((unsigned)__bfloat16_as_ushort(hy) << 16);
            hv.y = (unsigned)__bfloat16_as_ushort(hz)
                 | ((unsigned)__bfloat16_as_ushort(hw) << 16);
            lv.x = (unsigned)__bfloat16_as_ushort(lx)
                 | ((unsigned)__bfloat16_as_ushort(ly) << 16);
            lv.y = (unsigned)__bfloat16_as_ushort(lz)
                 | ((unsigned)__bfloat16_as_ushort(lw) << 16);
            *(uint2*)(Xh_s + row * LDX + col) = hv;
            *(uint2*)(Xl_s + row * LDX + col) = lv;
        }
        __syncthreads();

        // MMA over this chunk's K=128. B fragments read straight from global.
        for (int ks = 0; ks < 8; ks++) {
            int k0 = ks * 16;
            wmma::fragment<wmma::matrix_a, 16, 16, 16, __nv_bfloat16, wmma::row_major> ah[2], al[2];
            for (int i = 0; i < 2; i++) {
                int r = warp_row * 32 + i * 16;
                wmma::load_matrix_sync(ah[i], Xh_s + r * LDX + k0, LDX);
                wmma::load_matrix_sync(al[i], Xl_s + r * LDX + k0, LDX);
            }
            for (int j = 0; j < 2; j++) {
                int c = warp_col * 32 + j * 16;
                wmma::fragment<wmma::matrix_b, 16, 16, 16, __nv_bfloat16, wmma::col_major> bh, bl;
                wmma::load_matrix_sync(bh, WhC + c * 128 + k0, 128);
                wmma::load_matrix_sync(bl, WlC + c * 128 + k0, 128);
                for (int i = 0; i < 2; i++) {
                    wmma::mma_sync(acc[i][j], ah[i], bh, acc[i][j]);
                    wmma::mma_sync(acc[i][j], ah[i], bl, acc[i][j]);
                    wmma::mma_sync(acc[i][j], al[i], bh, acc[i][j]);
                }
            }
        }
    }
    __syncthreads();   // all MMA consumers done; Z aliases X stage

    // Store accumulators to Z
    for (int i = 0; i < 2; i++) {
        for (int j = 0; j < 2; j++) {
            int r = warp_row * 32 + i * 16;
            int c = warp_col * 32 + j * 16;
            wmma::store_matrix_sync(Z + r * LDZ + c, acc[i][j], LDZ, wmma::mem_row_major);
        }
    }
    __syncthreads();

    // LayerNorm stats: 4 threads per row, 32 cols each; add bias in-place.
    {
        int row = tid >> 2;
        int q = tid & 3;
        float sum = 0.f;
        float sq = 0.f;
        for (int c = 0; c < 32; c++) {
            int col = q * 32 + c;
            float z = Z[row * LDZ + col] + bias_s[col];
            Z[row * LDZ + col] = z;
            sum += z;
            sq += z * z;
        }
        sum += __shfl_xor_sync(0xffffffffu, sum, 1);
        sq += __shfl_xor_sync(0xffffffffu, sq, 1);
        sum += __shfl_xor_sync(0xffffffffu, sum, 2);
        sq += __shfl_xor_sync(0xffffffffu, sq, 2);
        if (q == 0) {
            float mean = sum * (1.0f / 128.0f);
            float var = sq * (1.0f / 128.0f) - mean * mean;
            mean_s[row] = mean;
            inv_s[row] = rsqrtf(var + 1e-5f);
        }
    }
    __syncthreads();

    // Coalesced normalize + store: 8 iters x 256 threads x float4
    for (int it = 0; it < 8; it++) {
        int g = it * 1024 + tid * 4;
        int row = g >> 7;
        int col = g & 127;
        int gr = row0 + row;
        if (gr < Nn) {
            float m = mean_s[row];
            float iv = inv_s[row];
            float4 o;
            o.x = (Z[row * LDZ + col + 0] - m) * iv * gamma_s[col + 0] + beta_s[col + 0];
            o.y = (Z[row * LDZ + col + 1] - m) * iv * gamma_s[col + 1] + beta_s[col + 1];
            o.z = (Z[row * LDZ + col + 2] - m) * iv * gamma_s[col + 2] + beta_s[col + 2];
            o.w = (Z[row * LDZ + col + 3] - m) * iv * gamma_s[col + 3] + beta_s[col + 3];
            *(float4*)(out + (long long)gr * DF + col) = o;
        }
    }
}

// ---------------------------------------------------------------------------
// Launch
// ---------------------------------------------------------------------------
extern "C" void kernel_launch(void* const* d_in, const int* in_sizes, int n_in,
                              void* d_out, int out_size) {
    const float* h      = (const float*)d_in[0];
    const int*   ei32   = (const int*)d_in[1];
    const float* deg    = (const float*)d_in[2];
    const float* Wself  = (const float*)d_in[3];
    const float* Wnb1   = (const float*)d_in[4];
    const float* Whp    = (const float*)d_in[5];
    const float* Wnb2   = (const float*)d_in[6];
    const float* bias   = (const float*)d_in[7];
    const float* logits = (const float*)d_in[8];
    const float* gamma  = (const float*)d_in[9];
    const float* beta   = (const float*)d_in[10];
    float*       out    = (float*)d_out;

    int Nn = in_sizes[2];
    long long E = in_sizes[1] / 2;

    float* agg1;
    float* agg2;
    __nv_bfloat16* Wh;
    __nv_bfloat16* Wl;
    int* cur;
    int* scan;
    int* bsum;
    int* rowptr;
    int* esrc;
    cudaGetSymbolAddress((void**)&agg1, g_agg1);
    cudaGetSymbolAddress((void**)&agg2, g_agg2);
    cudaGetSymbolAddress((void**)&Wh, g_Wh);
    cudaGetSymbolAddress((void**)&Wl, g_Wl);
    cudaGetSymbolAddress((void**)&cur, g_cur);
    cudaGetSymbolAddress((void**)&scan, g_scan);
    cudaGetSymbolAddress((void**)&bsum, g_bsum);
    cudaGetSymbolAddress((void**)&rowptr, g_rowptr);
    cudaGetSymbolAddress((void**)&esrc, g_esrc);

    const int T = 256;
    int nb_nodes = (Nn + T - 1) / T;
    int nb_edges = (int)((E + T - 1) / T);
    int nb_scan  = (Nn + SCAN_B - 1) / SCAN_B;
    int nb_agg   = (Nn * 32 + T - 1) / T;
    int fb       = (Nn + BMR - 1) / BMR;
    const int GEMM_SMEM = 36864;   // Xh + Xl stage (Z epilogue aliases it)

    cudaFuncSetAttribute(wmma_gemm_ln_kernel,
                         cudaFuncAttributeMaxDynamicSharedMemorySize, GEMM_SMEM);

    // Off critical path first
    weight_combine_kernel<<<64, T>>>(Wself, Wnb1, Whp, Wnb2, logits, Wh, Wl);
    detect_idx_kernel<<<1, 32>>>((const unsigned*)ei32);
    // CSR build from deg (no histogram pass needed)
    scan_a_kernel<<<nb_scan, SCAN_B>>>(deg, scan, bsum, Nn);
    scan_b_kernel<<<1, 1024>>>(bsum, nb_scan);
    scan_c_kernel<<<nb_nodes, T>>>(scan, bsum, deg, rowptr, cur, Nn);
    fill_kernel<<<nb_edges, T>>>(ei32, cur, esrc, E);
    // Aggregations (row range = [rowptr[w], cur[w]) after fill)
    agg_gather_kernel<<<nb_agg, T>>>(rowptr, cur, esrc, (const float4*)h,
                                     (float4*)agg1, deg, Nn);
    agg_gather_kernel<<<nb_agg, T>>>(rowptr, cur, esrc, (const float4*)agg1,
                                     (float4*)agg2, deg, Nn);
    // Fused GEMM + bias + LayerNorm
    wmma_gemm_ln_kernel<<<fb, 256, GEMM_SMEM>>>(h, agg1, agg2, Wh, Wl,
                                                bias, gamma, beta, out, Nn);
}